// round 3
// baseline (speedup 1.0000x reference)
#include <cuda_runtime.h>

// Problem constants
#define B_ 8
#define S_ 2048
#define D_ 512
#define Q_ 8
#define C_ 1024
#define T_ (B_*S_)            // 16384 tokens

// Tiling
#define TM 64                 // tokens per CTA
#define CN 128                // codes per chunk
#define KT 64                 // k tile
#define NTHREADS 512          // 16 warps: 2 k-half groups x 8 token-warps
#define RES_STRIDE (D_+4)     // 516
#define CB_STRIDE  (KT+4)     // 68
#define NTILES (Q_*(C_/CN)*(D_/KT))   // 512
#define NCTA (T_/TM)          // 256

typedef unsigned long long u64;

__device__ float g_part[NCTA*Q_];   // per-CTA loss partials (plain stores)

// smem layout (floats). s_comb: u64[8 warps][32 lanes][? ] -> we store the
// 4 j-partials packed per (warp,lane): [8][32][4] u64 = 8KB.
#define OFF_RES   0
#define OFF_CB    (OFF_RES + TM*RES_STRIDE)          // 2 buffers
#define OFF_CN    (OFF_CB + 2*CN*CB_STRIDE)
#define OFF_COMB  (OFF_CN + C_)                      // 8*32*4 u64 = 2048 floats*? (2048 u64 halves)
#define COMB_U64  (8*32*4)
#define OFF_IDX   (OFF_COMB + COMB_U64*2)
#define OFF_LOSS  (OFF_IDX + TM*Q_)
#define SMEM_FLOATS (OFF_LOSS + 16)
#define SMEM_BYTES  (SMEM_FLOATS*4)

__device__ __forceinline__ u64 ffma2(u64 a, u64 b, u64 c) {
    u64 d;
    asm("fma.rn.f32x2 %0, %1, %2, %3;" : "=l"(d) : "l"(a), "l"(b), "l"(c));
    return d;
}
__device__ __forceinline__ void cp_async16(float* smem_dst, const float* gsrc) {
    unsigned s = (unsigned)__cvta_generic_to_shared(smem_dst);
    asm volatile("cp.async.cg.shared.global [%0], [%1], 16;" :: "r"(s), "l"(gsrc));
}
#define CP_COMMIT() asm volatile("cp.async.commit_group;" ::: "memory")
#define CP_WAIT1()  asm volatile("cp.async.wait_group 1;" ::: "memory")

// issue cp.async for k-tile t into buf (128 codes x 64 k)
__device__ __forceinline__ void load_tile(const float* __restrict__ cbs,
                                          int t, float* buf, int tid) {
    int q     = t >> 6;                 // 64 tiles per q
    int rem   = t & 63;
    int code0 = (rem >> 3) * CN;        // 8 k-tiles per chunk
    int kt0   = (rem & 7) * KT;
    const float* base = cbs + (size_t)q*C_*D_ + kt0;
    #pragma unroll
    for (int it = 0; it < 4; it++) {
        int i   = tid + it*NTHREADS;    // 0..2047 16B chunks
        int row = i >> 4;
        int c4  = i & 15;
        cp_async16(buf + row*CB_STRIDE + c4*4,
                   base + (size_t)(code0+row)*D_ + c4*4);
    }
}

// ---------------------------------------------------------------------------
__global__ __launch_bounds__(NTHREADS, 1)
void rvq_main_kernel(const float* __restrict__ x,
                     const float* __restrict__ cbs,
                     float* __restrict__ out, int out_size) {
    extern __shared__ float smem[];
    float* s_res  = smem + OFF_RES;
    float* s_cb0  = smem + OFF_CB;
    float* s_cn   = smem + OFF_CN;
    u64*   s_comb = (u64*)(smem + OFF_COMB);   // [wh][lane][j]
    int*   s_idx  = (int*)(smem + OFF_IDX);
    float* s_loss = smem + OFF_LOSS;

    const int tid = threadIdx.x;
    const int w  = tid >> 5;
    const int l  = tid & 31;
    const int wh = w & 7;        // token-warp id (8 tokens each)
    const int kh = w >> 3;       // k-half: 0 or 1
    const size_t tok0 = (size_t)blockIdx.x * TM;
    float* bufs[2] = { s_cb0, s_cb0 + CN*CB_STRIDE };

    load_tile(cbs, 0, bufs[0], tid);
    CP_COMMIT();

    // x tile -> shared residual
    for (int i = tid; i < TM*(D_/4); i += NTHREADS) {
        int row = i >> 7;
        int c4  = i & 127;
        float4 v = ((const float4*)(x + (tok0+row)*D_))[c4];
        *(float4*)(s_res + row*RES_STRIDE + c4*4) = v;
    }

    int t = 0;
    for (int q = 0; q < Q_; q++) {
        const float* cbq = cbs + (size_t)q*C_*D_;

        // per-q code norms into s_cn (each CTA computes its own copy;
        // tile-loop barriers order these writes before the argmin reads)
        #pragma unroll
        for (int rr = 0; rr < C_/NTHREADS; rr++) {
            int r = tid + rr*NTHREADS;
            const float4* p = (const float4*)(cbq + (size_t)r*D_);
            float s = 0.f;
            #pragma unroll 8
            for (int i = 0; i < D_/4; i++) {
                float4 v = p[i];
                s = fmaf(v.x, v.x, s); s = fmaf(v.y, v.y, s);
                s = fmaf(v.z, v.z, s); s = fmaf(v.w, v.w, s);
            }
            s_cn[r] = s;
        }

        float best_s[8];
        int   best_i[8];
        #pragma unroll
        for (int i = 0; i < 8; i++) { best_s[i] = 3.4e38f; best_i[i] = 0x7fffffff; }

        for (int chunk = 0; chunk < C_/CN; chunk++) {
            const int code0 = chunk*CN;
            u64 acc[8][4];
            #pragma unroll
            for (int i = 0; i < 8; i++)
                #pragma unroll
                for (int j = 0; j < 4; j++) acc[i][j] = 0ull;

            for (int kti = 0; kti < D_/KT; kti++) {
                __syncthreads();
                if (t+1 < NTILES) load_tile(cbs, t+1, bufs[(t+1)&1], tid);
                CP_COMMIT();
                CP_WAIT1();
                __syncthreads();

                const float* cb   = bufs[t&1] + kh*32;
                const float* ares = s_res + (wh*8)*RES_STRIDE + kti*KT + kh*32;
                #pragma unroll
                for (int k4 = 0; k4 < 32; k4 += 4) {
                    ulonglong2 a[8];
                    #pragma unroll
                    for (int i = 0; i < 8; i++)
                        a[i] = *(const ulonglong2*)(ares + i*RES_STRIDE + k4);
                    ulonglong2 b[4];
                    #pragma unroll
                    for (int j = 0; j < 4; j++)
                        b[j] = *(const ulonglong2*)(cb + (l+32*j)*CB_STRIDE + k4);
                    #pragma unroll
                    for (int i = 0; i < 8; i++) {
                        #pragma unroll
                        for (int j = 0; j < 4; j++) {
                            acc[i][j] = ffma2(a[i].x, b[j].x, acc[i][j]);
                            acc[i][j] = ffma2(a[i].y, b[j].y, acc[i][j]);
                        }
                    }
                }
                t++;
            }

            // combine k-halves: for each token i (loop), warps 8..15 publish
            // their 4 j-partials lane-addressed; token-owner warps add.
            #pragma unroll
            for (int i = 0; i < 8; i++) {
                if (kh == 1) {
                    #pragma unroll
                    for (int j = 0; j < 4; j++)
                        s_comb[(wh*32 + l)*4 + j] = acc[i][j];
                }
                __syncthreads();
                if (kh == 0) {
                    float cn_ = 0.f; // placeholder to keep scope tidy
                    float bs = 3.4e38f; int bi = 0x7fffffff;
                    #pragma unroll
                    for (int j = 0; j < 4; j++) {
                        union { u64 u; float2 f; } me, ot;
                        me.u = acc[i][j];
                        ot.u = s_comb[(wh*32 + l)*4 + j];
                        float dot = (me.f.x + me.f.y) + (ot.f.x + ot.f.y);
                        float sc = fmaf(-2.f, dot, s_cn[code0 + l + 32*j]);
                        int ci = code0 + l + 32*j;
                        if (sc < bs || (sc == bs && ci < bi)) { bs = sc; bi = ci; }
                    }
                    #pragma unroll
                    for (int off = 16; off > 0; off >>= 1) {
                        float os = __shfl_down_sync(0xffffffffu, bs, off);
                        int   oi = __shfl_down_sync(0xffffffffu, bi, off);
                        if (os < bs || (os == bs && oi < bi)) { bs = os; bi = oi; }
                    }
                    bs = __shfl_sync(0xffffffffu, bs, 0);
                    bi = __shfl_sync(0xffffffffu, bi, 0);
                    if (bs < best_s[i] || (bs == best_s[i] && bi < best_i[i])) {
                        best_s[i] = bs; best_i[i] = bi;
                    }
                    (void)cn_;
                }
                __syncthreads();
            }
        }

        // residual update + loss (token-owner warps only)
        if (kh == 0) {
            float lloss = 0.f;
            #pragma unroll
            for (int i = 0; i < 8; i++) {
                const int tokr = wh*8 + i;
                const int bi = best_i[i];
                if (l == 0) s_idx[tokr*Q_ + q] = bi;
                const float* qc = cbq + (size_t)bi*D_;
                #pragma unroll
                for (int it = 0; it < 4; it++) {
                    int d4 = l*4 + it*128;
                    float4 cv = *(const float4*)(qc + d4);
                    float4 rv = *(float4*)(s_res + tokr*RES_STRIDE + d4);
                    rv.x -= cv.x; rv.y -= cv.y; rv.z -= cv.z; rv.w -= cv.w;
                    *(float4*)(s_res + tokr*RES_STRIDE + d4) = rv;
                    lloss = fmaf(rv.x, rv.x, lloss);
                    lloss = fmaf(rv.y, rv.y, lloss);
                    lloss = fmaf(rv.z, rv.z, lloss);
                    lloss = fmaf(rv.w, rv.w, lloss);
                }
            }
            #pragma unroll
            for (int off = 16; off > 0; off >>= 1)
                lloss += __shfl_down_sync(0xffffffffu, lloss, off);
            if (l == 0) s_loss[wh] = lloss;
        }
        __syncthreads();
        if (tid == 0) {
            float s = 0.f;
            #pragma unroll
            for (int i = 0; i < 8; i++) s += s_loss[i];
            g_part[blockIdx.x*Q_ + q] = s;
        }
        __syncthreads();
    }

    // quantized_out = x - residual_final
    for (int i = tid; i < TM*(D_/4); i += NTHREADS) {
        int row = i >> 7;
        int c4  = i & 127;
        float4 xv = ((const float4*)(x + (tok0+row)*D_))[c4];
        float4 rv = *(float4*)(s_res + row*RES_STRIDE + c4*4);
        ((float4*)(out + (tok0+row)*D_))[c4] =
            make_float4(xv.x-rv.x, xv.y-rv.y, xv.z-rv.z, xv.w-rv.w);
    }
    if (out_size >= (long long)T_*D_ + (long long)T_*Q_) {
        for (int i = tid; i < TM*Q_; i += NTHREADS)
            out[(size_t)T_*D_ + tok0*Q_ + i] = (float)s_idx[i];
    }
}

// ---------------------------------------------------------------------------
__global__ void rvq_fin_kernel(float* __restrict__ out, int out_size) {
    int q = threadIdx.x;
    if (q < Q_ && out_size >= (long long)T_*D_ + (long long)T_*Q_ + Q_) {
        float s = 0.f;
        for (int c = 0; c < NCTA; c++) s += g_part[c*Q_ + q];
        out[(size_t)T_*D_ + (size_t)T_*Q_ + q] = s / (float)((long long)T_*D_);
    }
}

// ---------------------------------------------------------------------------
extern "C" void kernel_launch(void* const* d_in, const int* in_sizes, int n_in,
                              void* d_out, int out_size) {
    const float* x;
    const float* cbs;
    if (in_sizes[0] == T_*D_) { x = (const float*)d_in[0]; cbs = (const float*)d_in[1]; }
    else                      { x = (const float*)d_in[1]; cbs = (const float*)d_in[0]; }
    float* out = (float*)d_out;

    cudaFuncSetAttribute(rvq_main_kernel,
                         cudaFuncAttributeMaxDynamicSharedMemorySize, SMEM_BYTES);

    rvq_main_kernel<<<NCTA, NTHREADS, SMEM_BYTES>>>(x, cbs, out, out_size);
    rvq_fin_kernel<<<1, 32>>>(out, out_size);
}

// round 7
// speedup vs baseline: 2.8868x; 2.8868x over previous
#include <cuda_runtime.h>
#include <cuda_bf16.h>
#include <cstdint>
#include <float.h>

// Problem constants
#define B_ 8
#define S_ 2048
#define D_ 512
#define Q_ 8
#define C_ 1024
#define T_ (B_*S_)            // 16384 tokens

#define TM 64                 // tokens per CTA (4 m-tiles of 16)
#define NCTA (T_/TM)          // 256
#define NTHREADS 256          // 8 warps = 4 m-tiles x 2 code-halves
#define NKS 32                // 512 / 16 k-steps
#define NT_ALL 128            // 1024 codes / 8
#define TAU 0.02f

// smem byte offsets
#define OFF_AHI  0            // [4 mt][32 ks][32 lane][4 u32] = 64KB
#define OFF_ALO  65536        // 64KB
#define OFF_B    131072       // 2 x 32KB chunks
#define OFF_CN   196608       // 1024 f32 = 4KB
#define OFF_T3   200704       // [2 nh][4 mt][16 row][6 u32] = 3072B
#define OFF_IDX  203776       // 64 int
#define OFF_NF   204032       // int
#define OFF_NP   204036       // int
#define OFF_FLAG 204040       // 64 int (full-rescore tokens)
#define OFF_PM   204296       // 64 int (pair tokens)
#define OFF_PC   204552       // 64 int (pair alt candidate)
#define OFF_RB   204808       // 8 float
#define OFF_RI   204840       // 8 int
#define OFF_LOSS 204872       // 8 float
#define SMEM_BYTES 204928

__device__ float    g_res[(size_t)T_*D_];                 // 32MB residual
__device__ unsigned g_bfrag[(size_t)Q_*NT_ALL*NKS*32*4];  // 16MB B fragments
__device__ float    g_cnorm[Q_*C_];
__device__ float    g_part[NCTA*Q_];

// ---------------------------------------------------------------------------
__device__ __forceinline__ void cp_async16(unsigned sdst, const void* gsrc) {
    asm volatile("cp.async.cg.shared.global [%0], [%1], 16;" :: "r"(sdst), "l"(gsrc));
}
#define CP_COMMIT() asm volatile("cp.async.commit_group;" ::: "memory")
#define CP_WAIT1()  asm volatile("cp.async.wait_group 1;" ::: "memory")
__device__ __forceinline__ unsigned smem_u32(const void* p) {
    unsigned a;
    asm("{ .reg .u64 t; cvta.to.shared.u64 t, %1; cvt.u32.u64 %0, t; }"
        : "=r"(a) : "l"(p));
    return a;
}
__device__ __forceinline__ void mma_bf16(float* c, unsigned a0, unsigned a1,
                                         unsigned a2, unsigned a3,
                                         unsigned b0, unsigned b1) {
    asm("mma.sync.aligned.m16n8k16.row.col.f32.bf16.bf16.f32 "
        "{%0,%1,%2,%3},{%4,%5,%6,%7},{%8,%9},{%0,%1,%2,%3};"
        : "+f"(c[0]), "+f"(c[1]), "+f"(c[2]), "+f"(c[3])
        : "r"(a0), "r"(a1), "r"(a2), "r"(a3), "r"(b0), "r"(b1));
}
__device__ __forceinline__ unsigned pack_hilo(float x0, float x1, unsigned& lo) {
    __nv_bfloat16 h0 = __float2bfloat16(x0);
    __nv_bfloat16 h1 = __float2bfloat16(x1);
    __nv_bfloat16 l0 = __float2bfloat16(x0 - __bfloat162float(h0));
    __nv_bfloat16 l1 = __float2bfloat16(x1 - __bfloat162float(h1));
    lo = (unsigned)__bfloat16_as_ushort(l0) | ((unsigned)__bfloat16_as_ushort(l1) << 16);
    return (unsigned)__bfloat16_as_ushort(h0) | ((unsigned)__bfloat16_as_ushort(h1) << 16);
}

struct Top3 { float s0, s1, s2; int i0, i1, i2; };
__device__ __forceinline__ void t3_init(Top3& t) {
    t.s0 = t.s1 = t.s2 = FLT_MAX; t.i0 = t.i1 = t.i2 = 0x7fffffff;
}
__device__ __forceinline__ void t3_ins(Top3& t, float s, int i) {
    if (s < t.s2 || (s == t.s2 && i < t.i2)) {
        if (s < t.s1 || (s == t.s1 && i < t.i1)) {
            t.s2 = t.s1; t.i2 = t.i1;
            if (s < t.s0 || (s == t.s0 && i < t.i0)) {
                t.s1 = t.s0; t.i1 = t.i0; t.s0 = s; t.i0 = i;
            } else { t.s1 = s; t.i1 = i; }
        } else { t.s2 = s; t.i2 = i; }
    }
}
__device__ __forceinline__ void t3_shxor(Top3& t, int m) {
    float s0 = __shfl_xor_sync(0xffffffffu, t.s0, m);
    float s1 = __shfl_xor_sync(0xffffffffu, t.s1, m);
    float s2 = __shfl_xor_sync(0xffffffffu, t.s2, m);
    int   i0 = __shfl_xor_sync(0xffffffffu, t.i0, m);
    int   i1 = __shfl_xor_sync(0xffffffffu, t.i1, m);
    int   i2 = __shfl_xor_sync(0xffffffffu, t.i2, m);
    t3_ins(t, s0, i0); t3_ins(t, s1, i1); t3_ins(t, s2, i2);
}

// ---------------------------------------------------------------------------
// Prep: code norms
// ---------------------------------------------------------------------------
__global__ void rvq_prep_norm(const float* __restrict__ cbs) {
    int r = blockIdx.x*blockDim.x + threadIdx.x;
    if (r < Q_*C_) {
        const float4* p = (const float4*)(cbs + (size_t)r*D_);
        float s = 0.f;
        #pragma unroll 8
        for (int i = 0; i < D_/4; i++) {
            float4 v = p[i];
            s = fmaf(v.x, v.x, s); s = fmaf(v.y, v.y, s);
            s = fmaf(v.z, v.z, s); s = fmaf(v.w, v.w, s);
        }
        g_cnorm[r] = s;
    }
}

// Prep: B fragments in mma register order: [q][nt][ks][lane]{bh0,bh1,bl0,bl1}
__global__ void rvq_prep_bfrag(const float* __restrict__ cbs) {
    int t = blockIdx.x*blockDim.x + threadIdx.x;
    if (t >= Q_*NT_ALL*NKS*32) return;
    int lane = t & 31;
    int ks   = (t >> 5) & 31;
    int nt   = (t >> 10) & 127;
    int q    = t >> 17;
    int code = nt*8 + (lane >> 2);
    int k0   = ks*16 + (lane & 3)*2;
    const float* cr = cbs + ((size_t)q*C_ + code)*D_;
    float2 v0 = *(const float2*)(cr + k0);
    float2 v1 = *(const float2*)(cr + k0 + 8);
    unsigned bl0, bl1;
    unsigned bh0 = pack_hilo(v0.x, v0.y, bl0);
    unsigned bh1 = pack_hilo(v1.x, v1.y, bl1);
    ((uint4*)g_bfrag)[t] = make_uint4(bh0, bh1, bl0, bl1);
}

// ---------------------------------------------------------------------------
// stage one B chunk (ng,kc): 16 nt (8 per half) x 4 ks = 32KB
// ---------------------------------------------------------------------------
__device__ __forceinline__ void stage_chunk(int q, int idx, unsigned sdst, int tid) {
    int ng = idx >> 3, kc = idx & 7;
    #pragma unroll
    for (int j = 0; j < 8; j++) {
        int c    = tid + j*NTHREADS;       // 0..2047
        int half = c >> 10;
        int i    = (c >> 7) & 7;
        int rem  = c & 127;                // ksl*32 + lane
        int nt   = half*64 + ng*8 + i;
        const uint4* src = (const uint4*)g_bfrag +
            ((((size_t)q*NT_ALL + nt)*NKS + kc*4)*32 + rem);
        cp_async16(sdst + (c << 4), src);
    }
}

// ---------------------------------------------------------------------------
__global__ __launch_bounds__(NTHREADS, 1)
void rvq_main(const float* __restrict__ x, const float* __restrict__ cbs,
              float* __restrict__ out, int out_size) {
    extern __shared__ char smem[];
    const unsigned sb = smem_u32(smem);
    float* s_cn   = (float*)(smem + OFF_CN);
    float* s_t3   = (float*)(smem + OFF_T3);
    int*   s_idx  = (int*)(smem + OFF_IDX);
    int*   s_nf   = (int*)(smem + OFF_NF);
    int*   s_np   = (int*)(smem + OFF_NP);
    int*   s_flag = (int*)(smem + OFF_FLAG);
    int*   s_pm   = (int*)(smem + OFF_PM);
    int*   s_pc   = (int*)(smem + OFF_PC);
    float* s_rb   = (float*)(smem + OFF_RB);
    int*   s_ri   = (int*)(smem + OFF_RI);
    float* s_loss = (float*)(smem + OFF_LOSS);

    const int tid  = threadIdx.x;
    const int wid  = tid >> 5;
    const int lane = tid & 31;
    const int mt   = wid & 3;        // m-tile
    const int nh   = wid >> 2;       // code half
    const size_t tok0 = (size_t)blockIdx.x * TM;

    for (int q = 0; q < Q_; q++) {
        const float* rsrc = q ? (const float*)g_res : x;
        const float* cbq  = cbs + (size_t)q*C_*D_;

        // ---- stage A fragments (hi/lo) + cnorm ----
        #pragma unroll 1
        for (int s = 0; s < 16; s++) {
            int slot = tid + s*NTHREADS;           // (mt,ks,lane)
            int smt = slot >> 10, sks = (slot >> 5) & 31, sls = slot & 31;
            int rowa = smt*16 + (sls >> 2);
            int k0 = sks*16 + (sls & 3)*2;
            const float* rp = rsrc + (tok0 + rowa)*D_ + k0;
            float2 v0 = *(const float2*)(rp);
            float2 v1 = *(const float2*)(rp + 8*D_);
            float2 v2 = *(const float2*)(rp + 8);
            float2 v3 = *(const float2*)(rp + 8*D_ + 8);
            unsigned l0, l1, l2, l3;
            unsigned h0 = pack_hilo(v0.x, v0.y, l0);
            unsigned h1 = pack_hilo(v1.x, v1.y, l1);
            unsigned h2 = pack_hilo(v2.x, v2.y, l2);
            unsigned h3 = pack_hilo(v3.x, v3.y, l3);
            *(uint4*)(smem + OFF_AHI + slot*16) = make_uint4(h0, h1, h2, h3);
            *(uint4*)(smem + OFF_ALO + slot*16) = make_uint4(l0, l1, l2, l3);
        }
        for (int i = tid; i < C_; i += NTHREADS) s_cn[i] = g_cnorm[q*C_ + i];
        if (tid == 0) { *s_nf = 0; *s_np = 0; }
        __syncthreads();

        stage_chunk(q, 0, sb + OFF_B, tid);
        CP_COMMIT();

        Top3 t3a, t3b;
        t3_init(t3a); t3_init(t3b);

        for (int ng = 0; ng < 8; ng++) {
            float acc[8][4];
            #pragma unroll
            for (int i = 0; i < 8; i++)
                #pragma unroll
                for (int j = 0; j < 4; j++) acc[i][j] = 0.f;

            for (int kc = 0; kc < 8; kc++) {
                int idx = ng*8 + kc;
                if (idx + 1 < 64)
                    stage_chunk(q, idx+1, sb + OFF_B + ((idx+1)&1)*32768, tid);
                CP_COMMIT();
                CP_WAIT1();
                __syncthreads();

                const char* bbase = smem + OFF_B + (idx&1)*32768 + nh*16384;
                #pragma unroll
                for (int ksl = 0; ksl < 4; ksl++) {
                    int ks = kc*4 + ksl;
                    unsigned aoff = (unsigned)(((mt*32 + ks)*32 + lane)*16);
                    uint4 AH = *(const uint4*)(smem + OFF_AHI + aoff);
                    uint4 AL = *(const uint4*)(smem + OFF_ALO + aoff);
                    #pragma unroll
                    for (int ntl = 0; ntl < 8; ntl++) {
                        uint4 Bv = *(const uint4*)(bbase + ntl*2048 + ksl*512 + lane*16);
                        mma_bf16(acc[ntl], AH.x, AH.y, AH.z, AH.w, Bv.x, Bv.y);
                        mma_bf16(acc[ntl], AH.x, AH.y, AH.z, AH.w, Bv.z, Bv.w);
                        mma_bf16(acc[ntl], AL.x, AL.y, AL.z, AL.w, Bv.x, Bv.y);
                    }
                }
                __syncthreads();
            }

            // epilogue: scores for this 64-code group
            int codebase = nh*512 + ng*64;
            #pragma unroll
            for (int ntl = 0; ntl < 8; ntl++) {
                int n0 = codebase + ntl*8 + (lane & 3)*2;
                float cn0 = s_cn[n0], cn1 = s_cn[n0+1];
                t3_ins(t3a, fmaf(-2.f, acc[ntl][0], cn0), n0);
                t3_ins(t3a, fmaf(-2.f, acc[ntl][1], cn1), n0+1);
                t3_ins(t3b, fmaf(-2.f, acc[ntl][2], cn0), n0);
                t3_ins(t3b, fmaf(-2.f, acc[ntl][3], cn1), n0+1);
            }
        }

        // quad merge (lanes with same C row)
        t3_shxor(t3a, 1); t3_shxor(t3a, 2);
        t3_shxor(t3b, 1); t3_shxor(t3b, 2);
        if ((lane & 3) == 0) {
            int r = lane >> 2;
            float* e = s_t3 + (((nh*4 + mt)*16) + r)*6;
            e[0] = t3a.s0; e[1] = t3a.s1; e[2] = t3a.s2;
            ((int*)e)[3] = t3a.i0; ((int*)e)[4] = t3a.i1; ((int*)e)[5] = t3a.i2;
            float* f = s_t3 + (((nh*4 + mt)*16) + r + 8)*6;
            f[0] = t3b.s0; f[1] = t3b.s1; f[2] = t3b.s2;
            ((int*)f)[3] = t3b.i0; ((int*)f)[4] = t3b.i1; ((int*)f)[5] = t3b.i2;
        }
        __syncthreads();

        // merge halves + decide (warps 0-3, lanes 0-15)
        if (nh == 0 && lane < 16) {
            const float* e0 = s_t3 + ((0*4 + mt)*16 + lane)*6;
            const float* e1 = s_t3 + ((1*4 + mt)*16 + lane)*6;
            Top3 t; t_init: ;
            t.s0 = e0[0]; t.s1 = e0[1]; t.s2 = e0[2];
            t.i0 = ((const int*)e0)[3]; t.i1 = ((const int*)e0)[4]; t.i2 = ((const int*)e0)[5];
            t3_ins(t, e1[0], ((const int*)e1)[3]);
            t3_ins(t, e1[1], ((const int*)e1)[4]);
            t3_ins(t, e1[2], ((const int*)e1)[5]);
            int token = mt*16 + lane;
            s_idx[token] = t.i0;
            if (t.s2 - t.s0 < TAU) {
                int p = atomicAdd(s_nf, 1);
                s_flag[p] = token;
            } else if (t.s1 - t.s0 < TAU) {
                int p = atomicAdd(s_np, 1);
                s_pm[p] = token; s_pc[p] = t.i1;
            }
        }
        __syncthreads();

        // ---- pair rescore: exact fp32 compare of top-2 (one warp each) ----
        int np = *s_np;
        for (int p = wid; p < np; p += 8) {
            int m = s_pm[p];
            int ca = s_idx[m], cb = s_pc[p];
            const float* rr = rsrc + (tok0 + m)*D_;
            const float* pa = cbq + (size_t)ca*D_;
            const float* pb = cbq + (size_t)cb*D_;
            float da = 0.f, db = 0.f;
            #pragma unroll
            for (int k = 0; k < 16; k++) {
                float rv = rr[lane*16 + k];
                da = fmaf(rv, pa[lane*16 + k], da);
                db = fmaf(rv, pb[lane*16 + k], db);
            }
            #pragma unroll
            for (int off = 16; off > 0; off >>= 1) {
                da += __shfl_down_sync(0xffffffffu, da, off);
                db += __shfl_down_sync(0xffffffffu, db, off);
            }
            if (lane == 0) {
                float sa = fmaf(-2.f, da, s_cn[ca]);
                float sc = fmaf(-2.f, db, s_cn[cb]);
                int win = (sc < sa || (sc == sa && cb < ca)) ? cb : ca;
                s_idx[m] = win;
            }
        }
        __syncthreads();

        // ---- full exact rescore (rare) ----
        int nf = *s_nf;
        for (int f = 0; f < nf; f++) {
            int m = s_flag[f];
            const float* rr = rsrc + (tok0 + m)*D_;
            float lb = FLT_MAX; int li = 0x7fffffff;
            #pragma unroll 1
            for (int jj = 0; jj < 4; jj++) {
                int code = wid*128 + jj*32 + lane;
                const float* cr = cbq + (size_t)code*D_;
                float dot = 0.f;
                #pragma unroll 8
                for (int d = 0; d < D_; d++) dot = fmaf(rr[d], cr[d], dot);
                float sc = fmaf(-2.f, dot, s_cn[code]);
                if (sc < lb || (sc == lb && code < li)) { lb = sc; li = code; }
            }
            #pragma unroll
            for (int off = 16; off > 0; off >>= 1) {
                float os = __shfl_down_sync(0xffffffffu, lb, off);
                int   oi = __shfl_down_sync(0xffffffffu, li, off);
                if (os < lb || (os == lb && oi < li)) { lb = os; li = oi; }
            }
            if (lane == 0) { s_rb[wid] = lb; s_ri[wid] = li; }
            __syncthreads();
            if (tid == 0) {
                float fb = FLT_MAX; int fi = 0x7fffffff;
                #pragma unroll
                for (int wv = 0; wv < 8; wv++)
                    if (s_rb[wv] < fb || (s_rb[wv] == fb && s_ri[wv] < fi)) {
                        fb = s_rb[wv]; fi = s_ri[wv];
                    }
                s_idx[m] = fi;
            }
            __syncthreads();
        }

        // ---- residual update + loss + index output ----
        float lloss = 0.f;
        #pragma unroll 1
        for (int i = 0; i < 8; i++) {
            int m = wid*8 + i;
            int idx = s_idx[m];
            const float* cr = cbq + (size_t)idx*D_;
            const float* rr = rsrc + (tok0 + m)*D_;
            float* wr = g_res + (tok0 + m)*D_;
            #pragma unroll
            for (int it = 0; it < 4; it++) {
                int d = it*128 + lane*4;
                float4 rv = *(const float4*)(rr + d);
                float4 cv = *(const float4*)(cr + d);
                float4 nv = make_float4(rv.x-cv.x, rv.y-cv.y, rv.z-cv.z, rv.w-cv.w);
                *(float4*)(wr + d) = nv;
                lloss = fmaf(nv.x, nv.x, lloss);
                lloss = fmaf(nv.y, nv.y, lloss);
                lloss = fmaf(nv.z, nv.z, lloss);
                lloss = fmaf(nv.w, nv.w, lloss);
            }
            if (lane == 0 && out_size >= (int)((long long)T_*D_ + (long long)T_*Q_))
                out[(size_t)T_*D_ + (tok0 + m)*Q_ + q] = (float)idx;
        }
        #pragma unroll
        for (int off = 16; off > 0; off >>= 1)
            lloss += __shfl_down_sync(0xffffffffu, lloss, off);
        if (lane == 0) s_loss[wid] = lloss;
        __syncthreads();
        if (tid == 0) {
            float s = 0.f;
            #pragma unroll
            for (int i = 0; i < 8; i++) s += s_loss[i];
            g_part[blockIdx.x*Q_ + q] = s;
        }
        __syncthreads();   // residual update visible before next q's A staging
    }

    // quantized_out = x - residual_final
    for (int i = tid; i < TM*(D_/4); i += NTHREADS) {
        int row = i >> 7, c4 = i & 127;
        float4 xv = ((const float4*)(x + (tok0+row)*D_))[c4];
        float4 rv = ((const float4*)(g_res + (tok0+row)*D_))[c4];
        ((float4*)(out + (tok0+row)*D_))[c4] =
            make_float4(xv.x-rv.x, xv.y-rv.y, xv.z-rv.z, xv.w-rv.w);
    }
}

// ---------------------------------------------------------------------------
__global__ void rvq_fin(float* __restrict__ out, int out_size) {
    int q = threadIdx.x;
    if (q < Q_ && out_size >= (int)((long long)T_*D_ + (long long)T_*Q_ + Q_)) {
        float s = 0.f;
        for (int c = 0; c < NCTA; c++) s += g_part[c*Q_ + q];
        out[(size_t)T_*D_ + (size_t)T_*Q_ + q] = s / (float)((long long)T_*D_);
    }
}

// ---------------------------------------------------------------------------
extern "C" void kernel_launch(void* const* d_in, const int* in_sizes, int n_in,
                              void* d_out, int out_size) {
    const float* x;
    const float* cbs;
    if (in_sizes[0] == T_*D_) { x = (const float*)d_in[0]; cbs = (const float*)d_in[1]; }
    else                      { x = (const float*)d_in[1]; cbs = (const float*)d_in[0]; }
    float* out = (float*)d_out;

    cudaFuncSetAttribute(rvq_main,
                         cudaFuncAttributeMaxDynamicSharedMemorySize, SMEM_BYTES);

    rvq_prep_norm<<<(Q_*C_ + 255)/256, 256>>>(cbs);
    rvq_prep_bfrag<<<(Q_*NT_ALL*NKS*32)/256, 256>>>(cbs);
    rvq_main<<<NCTA, NTHREADS, SMEM_BYTES>>>(x, cbs, out, out_size);
    rvq_fin<<<1, 32>>>(out, out_size);
}